// round 3
// baseline (speedup 1.0000x reference)
#include <cuda_runtime.h>

#define NN 4096
#define MM 128
#define KK 32
#define GG 16
#define NS 8
#define CHUNK (NN / NS)   // 512

// Scratch (device globals: no runtime allocation allowed)
__device__ float4 g_Asum4[NN * 256];           // reduced omega_child (16 MB)
__device__ float  g_V[NN * KK];                // transported-solve vectors v_i
__device__ float  g_partZ[MM * NS];
__device__ float  g_partCnt[MM * NS];
__device__ float  g_partS1[MM * NS * KK];
__device__ float  g_partS2[MM * NS * KK * KK];

// ---------------------------------------------------------------------------
// Kernel 0: pure streaming reduction of omega_child over G.
// 268 MB read, 16 MB written. Zero barriers -> max MLP -> near DRAM roofline.
// One thread per output float4 (4096*256 outputs), MLP=16 per thread.
// ---------------------------------------------------------------------------
__global__ void reduce_oc_kernel(const float4* __restrict__ oc4)
{
    const int gid = blockIdx.x * blockDim.x + threadIdx.x;  // 0..1048575
    const int i = gid >> 8;
    const int q = gid & 255;
    const float4* p = oc4 + (size_t)i * (GG * 256) + q;
    float4 s0 = p[0 * 256];
    float4 s1 = p[1 * 256];
    #pragma unroll
    for (int g = 2; g < GG; g += 2) {
        const float4 a = p[g * 256];
        const float4 b = p[(g + 1) * 256];
        s0.x += a.x; s0.y += a.y; s0.z += a.z; s0.w += a.w;
        s1.x += b.x; s1.y += b.y; s1.z += b.z; s1.w += b.w;
    }
    s0.x += s1.x; s0.y += s1.y; s0.z += s1.z; s0.w += s1.w;
    g_Asum4[gid] = s0;
}

// ---------------------------------------------------------------------------
// Kernel 1: per-i, solve (sum_g oc[i,g]) x = (sum_g mu[i,g])  -> v_i
// (1/G factors cancel.) Reads the pre-reduced A (16 MB) + mu (8 MB).
// ---------------------------------------------------------------------------
__global__ void solve_kernel(const float* __restrict__ mu_s)
{
    __shared__ float A[KK * 33];
    const int i = blockIdx.x;
    const int t = threadIdx.x;       // 0..127
    const int lane = t & 31, w = t >> 5;

    #pragma unroll
    for (int q = t; q < 256; q += 128) {
        const float4 s = g_Asum4[i * 256 + q];
        const int e = q * 4;
        const int r = e >> 5, c = e & 31;
        A[r * 33 + c + 0] = s.x;
        A[r * 33 + c + 1] = s.y;
        A[r * 33 + c + 2] = s.z;
        A[r * 33 + c + 3] = s.w;
    }
    if (t < KK) {
        const float* mu = mu_s + (size_t)i * GG * KK;
        float s = 0.f;
        #pragma unroll
        for (int g = 0; g < GG; g++) s += mu[g * KK + t];
        A[t * 33 + 32] = s;
    }
    __syncthreads();

    // Forward elimination (SPD: no pivoting). Column k read but never
    // written (left stale) -> no intra-warp RAW hazard on A[r][k].
    for (int k = 0; k < KK - 1; k++) {
        const float invp = 1.0f / A[k * 33 + k];
        const int c = k + 1 + lane;
        for (int r = k + 1 + w; r < KK; r += 4) {
            const float m = A[r * 33 + k] * invp;
            if (c <= 32) A[r * 33 + c] -= m * A[k * 33 + c];
        }
        __syncthreads();
    }

    // Backward Jordan on the b column only.
    for (int k = KK - 1; k >= 1; k--) {
        if (t < k) {
            const float xk = A[k * 33 + 32] / A[k * 33 + k];
            A[t * 33 + 32] -= A[t * 33 + k] * xk;
        }
        __syncthreads();
    }
    if (t < KK)
        g_V[(size_t)i * KK + t] = A[t * 33 + 32] / A[t * 33 + t];
}

// ---------------------------------------------------------------------------
// Kernel 2: per (cluster a, i-split s): accumulate
//   Z = sum w, cnt = sum mask, S1[l] = sum w v_l, S2[l,m] = sum w v_l v_m
// sqrt(w) trick: stage x = sqrt(w)*v once; S2 = sum x x^T.
// All W for the chunk is preloaded (no per-tile DRAM latency in the loop).
// Inner loop: 1 scalar LDS + 1 ld.shared.v2.b64 + 1 pack + 2 fma.rn.f32x2.
// ---------------------------------------------------------------------------
__global__ void accum_kernel(const float* __restrict__ W)
{
    const int a = blockIdx.x;
    const int s = blockIdx.y;
    const int t = threadIdx.x;     // 0..255
    const int i0base = s * CHUNK;

    __shared__ float sqw[CHUNK];        // sqrt of masked mean weights (2 KB)
    __shared__ float sx[32 * 36];       // sqrt(w)*v tile, row stride 36 (4.6 KB)
    __shared__ float s1part[8 * 32];
    __shared__ float zred[8], cred[8];

    // ---- Phase 0: preload + reduce all W for this chunk (2 i's per thread)
    float accZ = 0.f, accCnt = 0.f;
    #pragma unroll
    for (int r = 0; r < 2; r++) {
        const int il = t + r * 256;
        const float4* wp =
            (const float4*)(W + ((size_t)(i0base + il) * MM + a) * GG);
        const float4 w0 = wp[0], w1 = wp[1], w2 = wp[2], w3 = wp[3];
        const float sum = (w0.x + w0.y + w0.z + w0.w)
                        + (w1.x + w1.y + w1.z + w1.w)
                        + (w2.x + w2.y + w2.z + w2.w)
                        + (w3.x + w3.y + w3.z + w3.w);
        const float wm = sum * 0.0625f;
        const int ok = (wm >= 1e-6f);
        const float wmm = ok ? wm : 0.0f;
        sqw[il] = sqrtf(wmm);
        accZ += wmm;
        accCnt += ok ? 1.0f : 0.0f;
    }
    #pragma unroll
    for (int off = 16; off; off >>= 1) {
        accZ   += __shfl_xor_sync(0xffffffffu, accZ, off);
        accCnt += __shfl_xor_sync(0xffffffffu, accCnt, off);
    }
    if ((t & 31) == 0) { zred[t >> 5] = accZ; cred[t >> 5] = accCnt; }
    __syncthreads();

    const int l  = t >> 3;     // 0..31
    const int mg = t & 7;      // 0..7

    unsigned long long acc01 = 0ull, acc23 = 0ull;   // packed f32x2 accums
    float4 s1acc = make_float4(0.f, 0.f, 0.f, 0.f);

    const unsigned svbase = (unsigned)__cvta_generic_to_shared(sx);
    const int ii_s = t >> 3, c_s = t & 7;            // staging slot

    for (int tile = 0; tile < CHUNK / 32; tile++) {
        // stage x = sqrt(w) * v ; accumulate S1 contribution w*v = sqw*x
        {
            const int iloc = tile * 32 + ii_s;
            const float4 v =
                ((const float4*)g_V)[(size_t)(i0base + iloc) * 8 + c_s];
            const float sc = sqw[iloc];
            float4 x;
            x.x = sc * v.x; x.y = sc * v.y; x.z = sc * v.z; x.w = sc * v.w;
            s1acc.x += sc * x.x; s1acc.y += sc * x.y;
            s1acc.z += sc * x.z; s1acc.w += sc * x.w;
            *(float4*)(sx + ii_s * 36 + c_s * 4) = x;   // 16B aligned (144*ii+16*c)
        }
        __syncthreads();

        #pragma unroll
        for (int ii = 0; ii < 32; ii++) {
            const float xl = sx[ii * 36 + l];
            unsigned long long xm01, xm23, xl2;
            const unsigned addr = svbase + ii * 144 + mg * 16;
            asm volatile("ld.shared.v2.b64 {%0,%1}, [%2];"
                         : "=l"(xm01), "=l"(xm23) : "r"(addr));
            asm("mov.b64 %0, {%1,%2};" : "=l"(xl2) : "f"(xl), "f"(xl));
            asm("fma.rn.f32x2 %0, %1, %2, %0;" : "+l"(acc01)
                : "l"(xl2), "l"(xm01));
            asm("fma.rn.f32x2 %0, %1, %2, %0;" : "+l"(acc23)
                : "l"(xl2), "l"(xm23));
        }
        __syncthreads();
    }

    // ---- S2 partial: unpack and store (thread owns 4 unique (l,m) slots)
    {
        float a0, a1, a2, a3;
        asm("mov.b64 {%0,%1}, %2;" : "=f"(a0), "=f"(a1) : "l"(acc01));
        asm("mov.b64 {%0,%1}, %2;" : "=f"(a2), "=f"(a3) : "l"(acc23));
        float* p2 = g_partS2 + ((size_t)a * NS + s) * (KK * KK)
                  + l * KK + mg * 4;
        p2[0] = a0; p2[1] = a1; p2[2] = a2; p2[3] = a3;
    }

    // ---- S1: reduce over the 4 lanes sharing c (bits 3,4 of t), then warps
    #pragma unroll
    for (int off = 8; off <= 16; off <<= 1) {
        s1acc.x += __shfl_xor_sync(0xffffffffu, s1acc.x, off);
        s1acc.y += __shfl_xor_sync(0xffffffffu, s1acc.y, off);
        s1acc.z += __shfl_xor_sync(0xffffffffu, s1acc.z, off);
        s1acc.w += __shfl_xor_sync(0xffffffffu, s1acc.w, off);
    }
    if ((t & 24) == 0) {
        const int wrp = t >> 5, cc = t & 7;
        *(float4*)(s1part + wrp * 32 + cc * 4) = s1acc;
    }
    __syncthreads();
    if (t < 32) {
        float s1 = 0.f;
        #pragma unroll
        for (int wrp = 0; wrp < 8; wrp++) s1 += s1part[wrp * 32 + t];
        g_partS1[((size_t)a * NS + s) * KK + t] = s1;
    }
    if (t == 0) {
        float Z = 0.f, C = 0.f;
        #pragma unroll
        for (int ww = 0; ww < 8; ww++) { Z += zred[ww]; C += cred[ww]; }
        g_partZ[a * NS + s]   = Z;
        g_partCnt[a * NS + s] = C;
    }
}

// ---------------------------------------------------------------------------
// Kernel 3: per cluster a: psi_a = sum_lm S[l,m] * C[l,m]
//   S = op_avg^T op_avg,  C = S2/Zs - vbar vbar^T,  vbar = S1/Zs
// ---------------------------------------------------------------------------
__global__ void finalize_kernel(const float* __restrict__ omega_parent,
                                float* __restrict__ out)
{
    const int a = blockIdx.x;
    const int t = threadIdx.x;    // 0..255
    __shared__ float op[32 * 33];
    __shared__ float vbar[32];
    __shared__ float zc[2];
    __shared__ float red[8];

    {
        const float4* opp =
            (const float4*)(omega_parent + (size_t)a * GG * KK * KK);
        float4 sacc = make_float4(0.f, 0.f, 0.f, 0.f);
        #pragma unroll
        for (int g = 0; g < GG; g++) {
            const float4 v = opp[g * 256 + t];
            sacc.x += v.x; sacc.y += v.y; sacc.z += v.z; sacc.w += v.w;
        }
        const int e = t * 4;
        const int r = e >> 5, c = e & 31;
        const float inv = 1.0f / 16.0f;
        op[r * 33 + c + 0] = sacc.x * inv;
        op[r * 33 + c + 1] = sacc.y * inv;
        op[r * 33 + c + 2] = sacc.z * inv;
        op[r * 33 + c + 3] = sacc.w * inv;
    }
    if (t == 0) {
        float Z = 0.f, C = 0.f;
        #pragma unroll
        for (int ss = 0; ss < NS; ss++) {
            Z += g_partZ[a * NS + ss];
            C += g_partCnt[a * NS + ss];
        }
        zc[0] = (Z > 0.f) ? Z : 1.0f;
        zc[1] = C;
    }
    if (t < KK) {
        float s1 = 0.f;
        #pragma unroll
        for (int ss = 0; ss < NS; ss++)
            s1 += g_partS1[(a * NS + ss) * KK + t];
        vbar[t] = s1;
    }
    __syncthreads();
    const float Zs = zc[0];
    if (t < KK) vbar[t] = vbar[t] / Zs;
    __syncthreads();

    float psi = 0.f;
    #pragma unroll
    for (int j = 0; j < 4; j++) {
        const int e = t + 256 * j;
        const int l = e >> 5, m = e & 31;
        float s2 = 0.f;
        #pragma unroll
        for (int ss = 0; ss < NS; ss++)
            s2 += g_partS2[((size_t)a * NS + ss) * (KK * KK) + e];
        const float C = s2 / Zs - vbar[l] * vbar[m];
        float S = 0.f;
        #pragma unroll
        for (int k = 0; k < KK; k++)
            S += op[k * 33 + l] * op[k * 33 + m];
        psi += S * C;
    }

    #pragma unroll
    for (int off = 16; off; off >>= 1)
        psi += __shfl_xor_sync(0xffffffffu, psi, off);
    if ((t & 31) == 0) red[t >> 5] = psi;
    __syncthreads();
    if (t == 0) {
        float tot = 0.f;
        #pragma unroll
        for (int ww = 0; ww < 8; ww++) tot += red[ww];
        out[a] = (zc[1] >= 2.0f) ? tot : 0.0f;
    }
}

// ---------------------------------------------------------------------------
extern "C" void kernel_launch(void* const* d_in, const int* in_sizes, int n_in,
                              void* d_out, int out_size)
{
    const float* W  = (const float*)d_in[0];   // (N, M, G)
    const float* mu = (const float*)d_in[1];   // (N, G, K)
    const float* oc = (const float*)d_in[2];   // (N, G, K, K)
    const float* op = (const float*)d_in[3];   // (M, G, K, K)
    float* out = (float*)d_out;                // (M,)

    reduce_oc_kernel<<<NN, 256>>>((const float4*)oc);
    solve_kernel<<<NN, 128>>>(mu);
    accum_kernel<<<dim3(MM, NS), 256>>>(W);
    finalize_kernel<<<MM, 256>>>(op, out);
}

// round 4
// speedup vs baseline: 1.2710x; 1.2710x over previous
#include <cuda_runtime.h>

#define NN 4096
#define MM 128
#define KK 32
#define GG 16
#define NS 8
#define CHUNK (NN / NS)   // 512

// Scratch (device globals: no runtime allocation allowed)
__device__ float  g_V[NN * KK];                // transported-solve vectors v_i
__device__ float4 g_OP4[MM * 256];             // pre-reduced omega_parent mean
__device__ float  g_partZ[MM * NS];
__device__ float  g_partCnt[MM * NS];
__device__ float  g_partS1[MM * NS * KK];
__device__ float  g_partS2[MM * NS * KK * KK];

// ---------------------------------------------------------------------------
// Kernel 1 (fused): per-i reduce omega_child over G + solve A x = b -> v_i.
// TWO systems per block (256 threads): halves barrier overhead per i and
// doubles the load stream per block. (1/G factors cancel between A and b.)
// ---------------------------------------------------------------------------
__global__ void solve_kernel(const float* __restrict__ omega_child,
                             const float* __restrict__ mu_s)
{
    __shared__ float A[2][KK * 33];
    const int sub = threadIdx.x >> 7;      // which system
    const int tt  = threadIdx.x & 127;
    const int i = blockIdx.x * 2 + sub;
    const int lane = tt & 31, w = tt >> 5;
    float* Am = A[sub];

    // Load + reduce omega_child[i] over G (256 float4 per system)
    const float4* oc4 = (const float4*)(omega_child + (size_t)i * GG * KK * KK);
    #pragma unroll
    for (int q = tt; q < 256; q += 128) {
        float4 s0 = oc4[q];
        float4 s1 = oc4[256 + q];
        #pragma unroll
        for (int g = 2; g < GG; g += 2) {
            const float4 va = oc4[g * 256 + q];
            const float4 vb = oc4[(g + 1) * 256 + q];
            s0.x += va.x; s0.y += va.y; s0.z += va.z; s0.w += va.w;
            s1.x += vb.x; s1.y += vb.y; s1.z += vb.z; s1.w += vb.w;
        }
        s0.x += s1.x; s0.y += s1.y; s0.z += s1.z; s0.w += s1.w;
        const int e = q * 4;
        const int r = e >> 5, c = e & 31;
        Am[r * 33 + c + 0] = s0.x;
        Am[r * 33 + c + 1] = s0.y;
        Am[r * 33 + c + 2] = s0.z;
        Am[r * 33 + c + 3] = s0.w;
    }
    if (tt < KK) {
        const float* mu = mu_s + (size_t)i * GG * KK;
        float s = 0.f;
        #pragma unroll
        for (int g = 0; g < GG; g++) s += mu[g * KK + tt];
        Am[tt * 33 + 32] = s;
    }
    __syncthreads();

    // Forward elimination (SPD: no pivoting). Column k is read but never
    // written (left stale) -> no intra-warp RAW hazard on Am[r][k].
    for (int k = 0; k < KK - 1; k++) {
        const float invp = 1.0f / Am[k * 33 + k];
        const int c = k + 1 + lane;
        for (int r = k + 1 + w; r < KK; r += 4) {
            const float m = Am[r * 33 + k] * invp;
            if (c <= 32) Am[r * 33 + c] -= m * Am[k * 33 + c];
        }
        __syncthreads();
    }

    // Backward Jordan on the b column only.
    for (int k = KK - 1; k >= 1; k--) {
        if (tt < k) {
            const float xk = Am[k * 33 + 32] / Am[k * 33 + k];
            Am[tt * 33 + 32] -= Am[tt * 33 + k] * xk;
        }
        __syncthreads();
    }
    if (tt < KK)
        g_V[(size_t)i * KK + tt] = Am[tt * 33 + 32] / Am[tt * 33 + tt];
}

// ---------------------------------------------------------------------------
// Kernel 1b: streaming mean of omega_parent over G -> g_OP4 (512 KB).
// ---------------------------------------------------------------------------
__global__ void reduce_op_kernel(const float4* __restrict__ op4)
{
    const int gid = blockIdx.x * blockDim.x + threadIdx.x;  // 0..32767
    const int a = gid >> 8;
    const int q = gid & 255;
    const float4* p = op4 + (size_t)a * (GG * 256) + q;
    float4 s0 = p[0];
    float4 s1 = p[256];
    #pragma unroll
    for (int g = 2; g < GG; g += 2) {
        const float4 va = p[g * 256];
        const float4 vb = p[(g + 1) * 256];
        s0.x += va.x; s0.y += va.y; s0.z += va.z; s0.w += va.w;
        s1.x += vb.x; s1.y += vb.y; s1.z += vb.z; s1.w += vb.w;
    }
    const float inv = 1.0f / 16.0f;
    s0.x = (s0.x + s1.x) * inv; s0.y = (s0.y + s1.y) * inv;
    s0.z = (s0.z + s1.z) * inv; s0.w = (s0.w + s1.w) * inv;
    g_OP4[gid] = s0;
}

// ---------------------------------------------------------------------------
// Kernel 2: per (cluster a, i-split s): accumulate
//   Z = sum w, cnt = sum mask, S1[l] = sum w v_l, S2[l,m] = sum w v_l v_m
// sqrt(w) trick: stage x = sqrt(w)*v once; S2 = sum x x^T.
// 128 threads; thread owns a 2-row x 4-col register tile of S2:
//   rows {2rp, 2rp+1} (rp = t>>3), cols {4cq..4cq+3} (cq = t&7).
// Inner iter: ld.shared.v2.f32 (row pair, broadcast) + ld.shared.v2.b64
// (col quad) + 2 packs + 4 fma.rn.f32x2 = 8 issues for 256 MACs/warp.
// ---------------------------------------------------------------------------
__global__ void accum_kernel(const float* __restrict__ W)
{
    const int a = blockIdx.x;
    const int s = blockIdx.y;
    const int t = threadIdx.x;     // 0..127
    const int i0base = s * CHUNK;

    __shared__ float sqw[CHUNK];        // sqrt of masked mean weights (2 KB)
    __shared__ float sx[32 * 36];       // sqrt(w)*v tile, row stride 36
    __shared__ float zred[4], cred[4];

    // ---- Phase 0: preload + reduce all W for this chunk (4 i's per thread)
    float accZ = 0.f, accCnt = 0.f;
    #pragma unroll
    for (int r = 0; r < 4; r++) {
        const int il = t + r * 128;
        const float4* wp =
            (const float4*)(W + ((size_t)(i0base + il) * MM + a) * GG);
        const float4 w0 = wp[0], w1 = wp[1], w2 = wp[2], w3 = wp[3];
        const float sum = (w0.x + w0.y + w0.z + w0.w)
                        + (w1.x + w1.y + w1.z + w1.w)
                        + (w2.x + w2.y + w2.z + w2.w)
                        + (w3.x + w3.y + w3.z + w3.w);
        const float wm = sum * 0.0625f;
        const int ok = (wm >= 1e-6f);
        const float wmm = ok ? wm : 0.0f;
        sqw[il] = sqrtf(wmm);
        accZ += wmm;
        accCnt += ok ? 1.0f : 0.0f;
    }
    #pragma unroll
    for (int off = 16; off; off >>= 1) {
        accZ   += __shfl_xor_sync(0xffffffffu, accZ, off);
        accCnt += __shfl_xor_sync(0xffffffffu, accCnt, off);
    }
    if ((t & 31) == 0) { zred[t >> 5] = accZ; cred[t >> 5] = accCnt; }
    __syncthreads();
    if (t == 0) {
        float Z = zred[0] + zred[1] + zred[2] + zred[3];
        float C = cred[0] + cred[1] + cred[2] + cred[3];
        g_partZ[a * NS + s]   = Z;
        g_partCnt[a * NS + s] = C;
    }

    const int rp = t >> 3;      // 0..15 (row pair)
    const int cq = t & 7;       // 0..7  (col quad)
    const int ii_s = t >> 2;    // staging row 0..31
    const int cc_s = t & 3;     // staging quad 0..3 (handles cc and cc+4)

    unsigned long long acc00 = 0ull, acc01 = 0ull;   // row0: cols 0-1, 2-3
    unsigned long long acc10 = 0ull, acc11 = 0ull;   // row1
    float4 s1a = make_float4(0.f, 0.f, 0.f, 0.f);
    float4 s1b = make_float4(0.f, 0.f, 0.f, 0.f);

    const unsigned sxbase = (unsigned)__cvta_generic_to_shared(sx);
    const unsigned addr_l = sxbase + rp * 8;
    const unsigned addr_m = sxbase + cq * 16;

    for (int tile = 0; tile < CHUNK / 32; tile++) {
        // stage x = sqrt(w) * v ; accumulate S1 contribution w*v = sqw*x
        const int iloc = tile * 32 + ii_s;
        const float4* vp = (const float4*)g_V + (size_t)(i0base + iloc) * 8;
        const float4 v0 = vp[cc_s];
        const float4 v1 = vp[cc_s + 4];
        const float sc = sqw[iloc];
        float4 x0, x1;
        x0.x = sc * v0.x; x0.y = sc * v0.y; x0.z = sc * v0.z; x0.w = sc * v0.w;
        x1.x = sc * v1.x; x1.y = sc * v1.y; x1.z = sc * v1.z; x1.w = sc * v1.w;
        s1a.x += sc * x0.x; s1a.y += sc * x0.y;
        s1a.z += sc * x0.z; s1a.w += sc * x0.w;
        s1b.x += sc * x1.x; s1b.y += sc * x1.y;
        s1b.z += sc * x1.z; s1b.w += sc * x1.w;
        __syncthreads();                    // prev tile fully consumed
        *(float4*)(sx + ii_s * 36 + cc_s * 4)      = x0;   // cols 4cc..+3
        *(float4*)(sx + ii_s * 36 + 16 + cc_s * 4) = x1;   // cols 16+4cc..+3
        __syncthreads();

        #pragma unroll
        for (int ii = 0; ii < 32; ii++) {
            float xl0, xl1;
            asm volatile("ld.shared.v2.f32 {%0,%1}, [%2];"
                         : "=f"(xl0), "=f"(xl1) : "r"(addr_l + ii * 144));
            unsigned long long xm01, xm23;
            asm volatile("ld.shared.v2.b64 {%0,%1}, [%2];"
                         : "=l"(xm01), "=l"(xm23) : "r"(addr_m + ii * 144));
            unsigned long long xl0p, xl1p;
            asm("mov.b64 %0, {%1,%1};" : "=l"(xl0p) : "f"(xl0));
            asm("mov.b64 %0, {%1,%1};" : "=l"(xl1p) : "f"(xl1));
            asm("fma.rn.f32x2 %0, %1, %2, %0;" : "+l"(acc00) : "l"(xl0p), "l"(xm01));
            asm("fma.rn.f32x2 %0, %1, %2, %0;" : "+l"(acc01) : "l"(xl0p), "l"(xm23));
            asm("fma.rn.f32x2 %0, %1, %2, %0;" : "+l"(acc10) : "l"(xl1p), "l"(xm01));
            asm("fma.rn.f32x2 %0, %1, %2, %0;" : "+l"(acc11) : "l"(xl1p), "l"(xm23));
        }
    }

    // ---- S2 partial: thread owns 8 unique (l,m) slots (2 rows x 4 cols)
    {
        float b00, b01, b02, b03, b10, b11, b12, b13;
        asm("mov.b64 {%0,%1}, %2;" : "=f"(b00), "=f"(b01) : "l"(acc00));
        asm("mov.b64 {%0,%1}, %2;" : "=f"(b02), "=f"(b03) : "l"(acc01));
        asm("mov.b64 {%0,%1}, %2;" : "=f"(b10), "=f"(b11) : "l"(acc10));
        asm("mov.b64 {%0,%1}, %2;" : "=f"(b12), "=f"(b13) : "l"(acc11));
        float* p2 = g_partS2 + ((size_t)a * NS + s) * (KK * KK)
                  + (2 * rp) * KK + 4 * cq;
        *(float4*)p2        = make_float4(b00, b01, b02, b03);
        *(float4*)(p2 + KK) = make_float4(b10, b11, b12, b13);
    }

    // ---- S1: dump per-thread partials into sx (now free), reduce over ii
    __syncthreads();
    *(float4*)(sx + ii_s * 36 + cc_s * 4)      = s1a;
    *(float4*)(sx + ii_s * 36 + 16 + cc_s * 4) = s1b;
    __syncthreads();
    if (t < 32) {
        float ssum = 0.f;
        #pragma unroll
        for (int ii = 0; ii < 32; ii++) ssum += sx[ii * 36 + t];
        g_partS1[((size_t)a * NS + s) * KK + t] = ssum;
    }
}

// ---------------------------------------------------------------------------
// Kernel 3: per cluster a: psi_a = sum_lm S[l,m] * C[l,m]
//   S = op_avg^T op_avg,  C = S2/Zs - vbar vbar^T,  vbar = S1/Zs
// ---------------------------------------------------------------------------
__global__ void finalize_kernel(float* __restrict__ out)
{
    const int a = blockIdx.x;
    const int t = threadIdx.x;    // 0..255
    __shared__ float op[32 * 33];
    __shared__ float vbar[32];
    __shared__ float zc[2];
    __shared__ float red[8];

    {
        const float4 s = g_OP4[a * 256 + t];
        const int e = t * 4;
        const int r = e >> 5, c = e & 31;
        op[r * 33 + c + 0] = s.x;
        op[r * 33 + c + 1] = s.y;
        op[r * 33 + c + 2] = s.z;
        op[r * 33 + c + 3] = s.w;
    }
    if (t == 0) {
        float Z = 0.f, C = 0.f;
        #pragma unroll
        for (int ss = 0; ss < NS; ss++) {
            Z += g_partZ[a * NS + ss];
            C += g_partCnt[a * NS + ss];
        }
        zc[0] = (Z > 0.f) ? Z : 1.0f;
        zc[1] = C;
    }
    if (t < KK) {
        float s1 = 0.f;
        #pragma unroll
        for (int ss = 0; ss < NS; ss++)
            s1 += g_partS1[(a * NS + ss) * KK + t];
        vbar[t] = s1;
    }
    __syncthreads();
    const float Zs = zc[0];
    if (t < KK) vbar[t] = vbar[t] / Zs;
    __syncthreads();

    float psi = 0.f;
    #pragma unroll
    for (int j = 0; j < 4; j++) {
        const int e = t + 256 * j;
        const int l = e >> 5, m = e & 31;
        float s2 = 0.f;
        #pragma unroll
        for (int ss = 0; ss < NS; ss++)
            s2 += g_partS2[((size_t)a * NS + ss) * (KK * KK) + e];
        const float C = s2 / Zs - vbar[l] * vbar[m];
        float S = 0.f;
        #pragma unroll
        for (int k = 0; k < KK; k++)
            S += op[k * 33 + l] * op[k * 33 + m];
        psi += S * C;
    }

    #pragma unroll
    for (int off = 16; off; off >>= 1)
        psi += __shfl_xor_sync(0xffffffffu, psi, off);
    if ((t & 31) == 0) red[t >> 5] = psi;
    __syncthreads();
    if (t == 0) {
        float tot = 0.f;
        #pragma unroll
        for (int ww = 0; ww < 8; ww++) tot += red[ww];
        out[a] = (zc[1] >= 2.0f) ? tot : 0.0f;
    }
}

// ---------------------------------------------------------------------------
extern "C" void kernel_launch(void* const* d_in, const int* in_sizes, int n_in,
                              void* d_out, int out_size)
{
    const float* W  = (const float*)d_in[0];   // (N, M, G)
    const float* mu = (const float*)d_in[1];   // (N, G, K)
    const float* oc = (const float*)d_in[2];   // (N, G, K, K)
    const float* op = (const float*)d_in[3];   // (M, G, K, K)
    float* out = (float*)d_out;                // (M,)

    solve_kernel<<<NN / 2, 256>>>(oc, mu);
    reduce_op_kernel<<<MM, 256>>>((const float4*)op);
    accum_kernel<<<dim3(MM, NS), 128>>>(W);
    finalize_kernel<<<MM, 256>>>(out);
}